// round 10
// baseline (speedup 1.0000x reference)
#include <cuda_runtime.h>
#include <cuda_pipeline.h>

typedef unsigned long long ull;

// Problem dims
#define NC_  31
#define NXL  256
#define NYL  256
#define NO_  3
#define KXL  17
#define KYL  17
#define NG_  (NO_ * NC_)   // 93
#define WIN_ 9

// Compact weights: per (o,c) group a 9x9 tile of broadcast (v,v) float2 pairs
__device__ float2 g_w2[NG_ * 81];
__device__ int    g_ori[NG_];   // (kx0 << 8) | ky0

// ---------------------------------------------------------------------------
// Fused prep: one warp per group (origin via shfl-min, then scatter).
// ---------------------------------------------------------------------------
__global__ void prep_all(const float* __restrict__ vk,
                         const int* __restrict__ loc) {
    int w    = (blockIdx.x * blockDim.x + threadIdx.x) >> 5;
    int lane = threadIdx.x & 31;
    if (w >= NG_) return;

    int kxm = 1 << 30, kym = 1 << 30;
    int idxs[3]; float vs[3];
#pragma unroll
    for (int s = 0; s < 3; ++s) {
        int t = lane + 32 * s;
        if (t < 81) {
            int idx = loc[w * 81 + t];
            idxs[s] = idx;
            vs[s]   = vk[w * 81 + t];
            int ky = idx % KYL;
            int kx = (idx / KYL) % KXL;
            kxm = min(kxm, kx);
            kym = min(kym, ky);
        }
    }
#pragma unroll
    for (int off = 16; off; off >>= 1) {
        kxm = min(kxm, __shfl_xor_sync(0xffffffffu, kxm, off));
        kym = min(kym, __shfl_xor_sync(0xffffffffu, kym, off));
    }
    if (lane == 0) g_ori[w] = (kxm << 8) | kym;

#pragma unroll
    for (int s = 0; s < 3; ++s) {
        int t = lane + 32 * s;
        if (t < 81) {
            int idx = idxs[s];
            float v = fmaxf(vs[s], 0.0f);
            int ky = idx % KYL;
            int kx = (idx / KYL) % KXL;
            g_w2[w * 81 + (kx - kxm) * WIN_ + (ky - kym)] = make_float2(v, v);
        }
    }
}

// ---------------------------------------------------------------------------
// Main conv. Block = 256 threads, tile 32 rows x 128 cols per (b,o).
// Thread owns 2 output rows x 8 cols (txc = tid&15 col group, typ = tid>>4
// -> rows 2typ, 2typ+1). Staging: 4B cp.async at the TRUE window origin
// (any parity) -> single aligned math variant. Weight-major inner loop:
// weight row u (registers, loaded once) applied to input row u (out-row 0)
// and u+1 (out-row 1); input rows ping-pong in PA/PB register sets, each of
// the 10 rows loaded once as 4 swizzled LDS.128. Dual-phase fma.rn.f32x2.
// ---------------------------------------------------------------------------
#define TH 32
#define TW 128
#define SRO 40                 // staged rows (TH + 8)
#define SWF 160                // smem row stride in floats
#define ROWB (SWF * 4)         // 640 bytes
#define TILE_B (SRO * ROWB)    // 25600 bytes
#define WPAD 10                // weight row stride in ull
#define WBUF (WIN_ * WPAD)     // 90 ull
#define SMEM_BYTES (2 * TILE_B + 2 * WBUF * 8 + NC_ * 4)  // 52764

#define FMA2(acc, a, b) \
    asm("fma.rn.f32x2 %0, %1, %2, %0;" : "+l"(acc) : "l"(a), "l"(b))

__device__ __forceinline__ int swz_unit(int cu) {
    return cu ^ ((cu >> 3) & 7);
}

__device__ __forceinline__ void ldE(const char* p, ull& a, ull& b) {
    longlong2 L = *(const longlong2*)p;
    a = (ull)L.x; b = (ull)L.y;
}

// 4 A-FMAs (pairs t..t+3) and 5 B-FMAs (pairs t..t+4), one weight each
#define GA(acc, P, t, w) { FMA2(acc[0], P[t], w); FMA2(acc[1], P[t+1], w); \
                           FMA2(acc[2], P[t+2], w); FMA2(acc[3], P[t+3], w); }
#define GB(acc, P, t, w) { FMA2(acc[0], P[t], w); FMA2(acc[1], P[t+1], w); \
                           FMA2(acc[2], P[t+2], w); FMA2(acc[3], P[t+3], w); \
                           FMA2(acc[4], P[t+4], w); }

// One channel: 9 weight rows applied to rows (u, u+1) of the staged tile.
__device__ __forceinline__ void channel_math(
        const char* __restrict__ tb, const char* __restrict__ wb,
        const int* offs,
        ull* a0A, ull* a0B, ull* a1A, ull* a1B) {
    ull PA[8], PB[8];
#pragma unroll
    for (int e = 0; e < 4; ++e) ldE(tb + offs[e], PA[2*e], PA[2*e+1]);
#pragma unroll
    for (int e = 0; e < 4; ++e) ldE(tb + offs[e] + ROWB, PB[2*e], PB[2*e+1]);

#pragma unroll
    for (int u = 0; u < 9; ++u) {
        ull* P0 = (u & 1) ? PB : PA;   // input row u   (out-row 0, tap u)
        ull* P1 = (u & 1) ? PA : PB;   // input row u+1 (out-row 1, tap u)
        const char* wr = wb + u * 80;
        const int rn = (u + 2) * ROWB;

        ull w0, w1, w2, w3, w4, w5, w6, w7;
        ldE(wr,      w0, w1);
        ldE(wr + 16, w2, w3);

        GA(a0A, P0, 0, w0); GA(a1A, P1, 0, w0);
        GB(a0B, P0, 0, w1); GB(a1B, P1, 0, w1);
        ldE(wr + 32, w4, w5);
        GA(a0A, P0, 1, w2); GA(a1A, P1, 1, w2);
        GB(a0B, P0, 1, w3); GB(a1B, P1, 1, w3);
        if (u < 8) ldE(tb + offs[0] + rn, P0[0], P0[1]);   // unit0, row u+2
        ldE(wr + 48, w6, w7);
        GA(a0A, P0, 2, w4); GA(a1A, P1, 2, w4);
        GB(a0B, P0, 2, w5); GB(a1B, P1, 2, w5);
        GA(a0A, P0, 3, w6); GA(a1A, P1, 3, w6);
        GB(a0B, P0, 3, w7); GB(a1B, P1, 3, w7);
        if (u < 8) ldE(tb + offs[1] + rn, P0[2], P0[3]);   // unit1, row u+2
        const ull w8 = *(const ull*)(wr + 64);
        GA(a0A, P0, 4, w8); GA(a1A, P1, 4, w8);
        if (u < 8) {
            ldE(tb + offs[2] + rn, P0[4], P0[5]);          // unit2, row u+2
            ldE(tb + offs[3] + rn, P0[6], P0[7]);          // unit3, row u+2
        }
    }
}

__global__ void __launch_bounds__(256, 3) conv_kernel(
        const float* __restrict__ x, float* __restrict__ out) {
    extern __shared__ float smem[];
    char* buf0 = (char*)smem;
    char* buf1 = buf0 + TILE_B;
    char* wb0  = buf1 + TILE_B;
    char* wb1  = wb0 + WBUF * 8;
    int*  s_ori = (int*)(wb1 + WBUF * 8);

    const int tid = threadIdx.x;
    const int tx  = tid & 7;          // staging col phase
    const int ty  = tid >> 3;         // staging row
    const int txc = tid & 15;         // compute: 8-col group
    const int typ = tid >> 4;         // compute: row pair 2typ, 2typ+1

    const int o  = blockIdx.y;
    const int b  = blockIdx.z;
    const int i0 = (blockIdx.x >> 1) * TH;
    const int j0 = (blockIdx.x & 1) * TW;

    if (tid < NC_) s_ori[tid] = g_ori[o * NC_ + tid];
    __syncthreads();

    const float* __restrict__ xb = x + (size_t)b * NC_ * NXL * NYL;
    const int wdoff = ((tid / WIN_) * WPAD + tid % WIN_) * 8;
    const int thcu  = tx >> 2;        // 0/1
    const int off4  = (tx & 3) * 4;   // within-unit byte offset

    // ---- async staging of one channel: 4B granular, TRUE origin ----
    auto stage = [&](int c, char* tbuf, char* wbuf) {
        const int ori = s_ori[c];
        const int kx0 = ori >> 8, ky0 = ori & 255;
        const int A   = j0 + ky0 - 8;          // gmem col of staged col 0
        const int ri0 = i0 + kx0 - 8;
        const float* __restrict__ xc = xb + (size_t)c * (NXL * NYL);
#pragma unroll
        for (int pass = 0; pass < 2; ++pass) {
            if (pass == 1 && ty >= 8) break;
            const int r  = ty + pass * 32;
            const int gi = ri0 + r;
            const bool rowok = (unsigned)gi < NXL;
            const float* grow = xc + (rowok ? gi : 0) * NYL;
            char* rb = tbuf + r * ROWB + off4;
#pragma unroll
            for (int k = 0; k < 17; ++k) {
                const int gcol = A + tx + 8 * k;
                const bool ok  = rowok && ((unsigned)gcol < NYL);
                const int dst  = swz_unit(thcu + 2 * k) * 16;
                __pipeline_memcpy_async(rb + dst,
                                        ok ? grow + gcol : (const float*)xc,
                                        4, ok ? 0 : 4);
            }
        }
        if (tid < 81)
            __pipeline_memcpy_async(wbuf + wdoff,
                                    ((const ull*)g_w2)
                                        + (size_t)(o * NC_ + c) * 81 + tid,
                                    8);
        __pipeline_commit();
    };

    // per-thread swizzled E unit byte offsets for row 2typ (row-independent)
    int offs[4];
#pragma unroll
    for (int e = 0; e < 4; ++e)
        offs[e] = (2 * typ) * ROWB + swz_unit(2 * txc + e) * 16;

    ull a0A[4], a0B[5], a1A[4], a1B[5];
#pragma unroll
    for (int j = 0; j < 4; ++j) { a0A[j] = 0ull; a1A[j] = 0ull; }
#pragma unroll
    for (int i = 0; i < 5; ++i) { a0B[i] = 0ull; a1B[i] = 0ull; }

    stage(0, buf0, wb0);
    __pipeline_wait_prior(0);
    __syncthreads();

    for (int c = 0; c < NC_; ++c) {
        if (c + 1 < NC_)
            stage(c + 1, (c & 1) ? buf0 : buf1, (c & 1) ? wb0 : wb1);

        channel_math((c & 1) ? buf1 : buf0, (c & 1) ? wb1 : wb0,
                     offs, a0A, a0B, a1A, a1B);

        __pipeline_wait_prior(0);
        __syncthreads();
    }

    // ---- epilogue: merge dual-phase accumulators, write 2 rows x 8 cols ----
    const size_t orow = (size_t)(b * NO_ + o) * NXL + (i0 + 2 * typ);
    float* op0 = out + orow * NYL + j0 + txc * 8;
    float* op1 = op0 + NYL;
    float r0[8], r1[8];
#pragma unroll
    for (int j = 0; j < 4; ++j) {
        r0[2*j]   = __uint_as_float((unsigned)(a0A[j] & 0xffffffffull))
                  + __uint_as_float((unsigned)(a0B[j] >> 32));
        r0[2*j+1] = __uint_as_float((unsigned)(a0A[j] >> 32))
                  + __uint_as_float((unsigned)(a0B[j+1] & 0xffffffffull));
        r1[2*j]   = __uint_as_float((unsigned)(a1A[j] & 0xffffffffull))
                  + __uint_as_float((unsigned)(a1B[j] >> 32));
        r1[2*j+1] = __uint_as_float((unsigned)(a1A[j] >> 32))
                  + __uint_as_float((unsigned)(a1B[j+1] & 0xffffffffull));
    }
    reinterpret_cast<float4*>(op0)[0] = make_float4(r0[0], r0[1], r0[2], r0[3]);
    reinterpret_cast<float4*>(op0)[1] = make_float4(r0[4], r0[5], r0[6], r0[7]);
    reinterpret_cast<float4*>(op1)[0] = make_float4(r1[0], r1[1], r1[2], r1[3]);
    reinterpret_cast<float4*>(op1)[1] = make_float4(r1[4], r1[5], r1[6], r1[7]);
}

// ---------------------------------------------------------------------------
extern "C" void kernel_launch(void* const* d_in, const int* in_sizes, int n_in,
                              void* d_out, int out_size) {
    const float* x   = (const float*)d_in[0];
    const float* vk  = (const float*)d_in[1];
    const int*   loc = (const int*)d_in[2];
    float* out = (float*)d_out;

    cudaFuncSetAttribute(conv_kernel,
                         cudaFuncAttributeMaxDynamicSharedMemorySize,
                         SMEM_BYTES);

    prep_all<<<(NG_ * 32 + 255) / 256, 256>>>(vk, loc);

    dim3 grid((NXL / TH) * (NYL / TW), NO_, 16);  // (16, 3, 16)
    conv_kernel<<<grid, 256, SMEM_BYTES>>>(x, out);
}

// round 11
// speedup vs baseline: 1.0419x; 1.0419x over previous
#include <cuda_runtime.h>
#include <cuda_pipeline.h>

typedef unsigned long long ull;

// Problem dims
#define NC_  31
#define NXL  256
#define NYL  256
#define NO_  3
#define KXL  17
#define KYL  17
#define NG_  (NO_ * NC_)   // 93
#define WIN_ 9

// Compact weights: per (o,c) group a 9x9 tile of broadcast (v,v) float2 pairs
__device__ float2 g_w2[NG_ * 81];
__device__ int    g_ori[NG_];   // (kx0 << 8) | ky0

// ---------------------------------------------------------------------------
// Fused prep: one warp per group (origin via shfl-min, then scatter).
// ---------------------------------------------------------------------------
__global__ void prep_all(const float* __restrict__ vk,
                         const int* __restrict__ loc) {
    int w    = (blockIdx.x * blockDim.x + threadIdx.x) >> 5;
    int lane = threadIdx.x & 31;
    if (w >= NG_) return;

    int kxm = 1 << 30, kym = 1 << 30;
    int idxs[3]; float vs[3];
#pragma unroll
    for (int s = 0; s < 3; ++s) {
        int t = lane + 32 * s;
        if (t < 81) {
            int idx = loc[w * 81 + t];
            idxs[s] = idx;
            vs[s]   = vk[w * 81 + t];
            int ky = idx % KYL;
            int kx = (idx / KYL) % KXL;
            kxm = min(kxm, kx);
            kym = min(kym, ky);
        }
    }
#pragma unroll
    for (int off = 16; off; off >>= 1) {
        kxm = min(kxm, __shfl_xor_sync(0xffffffffu, kxm, off));
        kym = min(kym, __shfl_xor_sync(0xffffffffu, kym, off));
    }
    if (lane == 0) g_ori[w] = (kxm << 8) | kym;

#pragma unroll
    for (int s = 0; s < 3; ++s) {
        int t = lane + 32 * s;
        if (t < 81) {
            int idx = idxs[s];
            float v = fmaxf(vs[s], 0.0f);
            int ky = idx % KYL;
            int kx = (idx / KYL) % KXL;
            g_w2[w * 81 + (kx - kxm) * WIN_ + (ky - kym)] = make_float2(v, v);
        }
    }
}

// ---------------------------------------------------------------------------
// Main conv = r10 dual-row weight-major math + r9 8B-aligned parity staging.
// Block = 256 threads, tile 32 rows x 128 cols per (b,o).
// Compute thread: txc = tid&15 (8-col group), typ = tid>>4 (rows 2typ,2typ+1).
// Staged col = out_col + v + S with S = ky0&1; SV0: even taps->accA aligned,
// odd->accB. SV1: roles flip and pair range extends by one (9 pairs/row).
// Input rows ping-pong in PA/PB; each of the 10 rows loaded once per channel.
// Weight row u (broadcast LDS.128) serves both output rows. fma.rn.f32x2.
// ---------------------------------------------------------------------------
#define TH 32
#define TW 128
#define SRO 40                 // staged rows (TH + 8)
#define SWF 160                // smem row stride in floats
#define ROWB (SWF * 4)         // 640 bytes
#define TILE_B (SRO * ROWB)    // 25600 bytes
#define WPAD 10                // weight row stride in ull
#define WBUF (WIN_ * WPAD)     // 90 ull
#define SMEM_BYTES (2 * TILE_B + 2 * WBUF * 8 + NC_ * 4)  // 52764

#define FMA2(acc, a, b) \
    asm("fma.rn.f32x2 %0, %1, %2, %0;" : "+l"(acc) : "l"(a), "l"(b))

__device__ __forceinline__ int swz_unit(int cu) {
    return cu ^ ((cu >> 3) & 7);
}

__device__ __forceinline__ void ldE(const char* p, ull& a, ull& b) {
    longlong2 L = *(const longlong2*)(p);
    a = (ull)L.x; b = (ull)L.y;
}

// 4 A-FMAs (pairs t..t+3) and 5 B-FMAs (pairs t..t+4), one weight each
#define GA(acc, P, t, w) { FMA2(acc[0], P[t]); } // placeholder (redefined)
#undef GA
#define GA(acc, P, t, w) { FMA2(acc[0], P[(t)], w);   FMA2(acc[1], P[(t)+1], w); \
                           FMA2(acc[2], P[(t)+2], w); FMA2(acc[3], P[(t)+3], w); }
#define GB(acc, P, t, w) { FMA2(acc[0], P[(t)], w);   FMA2(acc[1], P[(t)+1], w); \
                           FMA2(acc[2], P[(t)+2], w); FMA2(acc[3], P[(t)+3], w); \
                           FMA2(acc[4], P[(t)+4], w); }

// One channel, parity SV. P0 = input row u regs, P1 = row u+1 (ping-pong).
template<int SV>
__device__ __forceinline__ void channel_math(
        const char* __restrict__ tb, const char* __restrict__ wb,
        const int* offs,
        ull* a0A, ull* a0B, ull* a1A, ull* a1B) {
    ull PA[9], PB[9];
#pragma unroll
    for (int e = 0; e < 4; ++e) ldE(tb + offs[e], PA[2*e], PA[2*e+1]);
#pragma unroll
    for (int e = 0; e < 4; ++e) ldE(tb + offs[e] + ROWB, PB[2*e], PB[2*e+1]);
    if (SV == 1) {
        PA[8] = *(const ull*)(tb + offs[4]);
        PB[8] = *(const ull*)(tb + offs[4] + ROWB);
    }

#pragma unroll
    for (int u = 0; u < 9; ++u) {
        ull* P0 = (u & 1) ? PB : PA;   // input row u   (tap u for out-row 0)
        ull* P1 = (u & 1) ? PA : PB;   // input row u+1 (tap u for out-row 1)
        const char* wr = wb + u * 80;
        const int rn = (u + 2) * ROWB;

        ull w0, w1, w2, w3, w4, w5, w6, w7;
        ldE(wr,      w0, w1);
        ldE(wr + 16, w2, w3);

        if (SV == 0) {
            GA(a0A, P0, 0, w0); GA(a1A, P1, 0, w0);
            GB(a0B, P0, 0, w1); GB(a1B, P1, 0, w1);
            ldE(wr + 32, w4, w5);
            GA(a0A, P0, 1, w2); GA(a1A, P1, 1, w2);
            GB(a0B, P0, 1, w3); GB(a1B, P1, 1, w3);
            if (u < 8) ldE(tb + offs[0] + rn, P0[0], P0[1]);
            ldE(wr + 48, w6, w7);
            GA(a0A, P0, 2, w4); GA(a1A, P1, 2, w4);
            GB(a0B, P0, 2, w5); GB(a1B, P1, 2, w5);
            GA(a0A, P0, 3, w6); GA(a1A, P1, 3, w6);
            GB(a0B, P0, 3, w7); GB(a1B, P1, 3, w7);
            if (u < 8) ldE(tb + offs[1] + rn, P0[2], P0[3]);
            const ull w8 = *(const ull*)(wr + 64);
            GA(a0A, P0, 4, w8); GA(a1A, P1, 4, w8);
            if (u < 8) {
                ldE(tb + offs[2] + rn, P0[4], P0[5]);
                ldE(tb + offs[3] + rn, P0[6], P0[7]);
            }
        } else {
            GB(a0B, P0, 0, w0); GB(a1B, P1, 0, w0);
            GA(a0A, P0, 1, w1); GA(a1A, P1, 1, w1);
            ldE(wr + 32, w4, w5);
            GB(a0B, P0, 1, w2); GB(a1B, P1, 1, w2);
            GA(a0A, P0, 2, w3); GA(a1A, P1, 2, w3);
            if (u < 8) ldE(tb + offs[0] + rn, P0[0], P0[1]);
            ldE(wr + 48, w6, w7);
            GB(a0B, P0, 2, w4); GB(a1B, P1, 2, w4);
            GA(a0A, P0, 3, w5); GA(a1A, P1, 3, w5);
            GB(a0B, P0, 3, w6); GB(a1B, P1, 3, w6);
            GA(a0A, P0, 4, w7); GA(a1A, P1, 4, w7);
            if (u < 8) ldE(tb + offs[1] + rn, P0[2], P0[3]);
            const ull w8 = *(const ull*)(wr + 64);
            GB(a0B, P0, 4, w8); GB(a1B, P1, 4, w8);
            if (u < 8) {
                ldE(tb + offs[2] + rn, P0[4], P0[5]);
                ldE(tb + offs[3] + rn, P0[6], P0[7]);
                P0[8] = *(const ull*)(tb + offs[4] + rn);
            }
        }
    }
}

__global__ void __launch_bounds__(256, 3) conv_kernel(
        const float* __restrict__ x, float* __restrict__ out) {
    extern __shared__ float smem[];
    char* buf0 = (char*)smem;
    char* buf1 = buf0 + TILE_B;
    char* wb0  = buf1 + TILE_B;
    char* wb1  = wb0 + WBUF * 8;
    int*  s_ori = (int*)(wb1 + WBUF * 8);

    const int tid = threadIdx.x;
    const int tx  = tid & 7;          // staging col phase
    const int ty  = tid >> 3;         // staging row
    const int txc = tid & 15;         // compute: 8-col group
    const int typ = tid >> 4;         // compute: row pair 2typ, 2typ+1

    const int o  = blockIdx.y;
    const int b  = blockIdx.z;
    const int i0 = (blockIdx.x >> 1) * TH;
    const int j0 = (blockIdx.x & 1) * TW;

    if (tid < NC_) s_ori[tid] = g_ori[o * NC_ + tid];
    __syncthreads();

    const float* __restrict__ xb = x + (size_t)b * NC_ * NXL * NYL;
    const int wdoff = ((tid / WIN_) * WPAD + tid % WIN_) * 8;
    const int half8 = (tx & 1) * 8;
    const int thcu  = tx >> 1;

    // ---- r9 staging: 8B cp.async from even (8B-aligned) origin ----
    auto stage = [&](int c, char* tbuf, char* wbuf) {
        const int ori = s_ori[c];
        const int kx0 = ori >> 8, ky0 = ori & 255;
        const int A   = j0 + (ky0 & ~1) - 8;   // even gmem origin
        const int ri0 = i0 + kx0 - 8;
        const float* __restrict__ xc = xb + (size_t)c * (NXL * NYL);
#pragma unroll
        for (int pass = 0; pass < 2; ++pass) {
            if (pass == 1 && ty >= 8) break;
            const int r  = ty + pass * 32;
            const int gi = ri0 + r;
            const bool rowok = (unsigned)gi < NXL;
            const float* grow = xc + (rowok ? gi : 0) * NYL;
            char* rb = tbuf + r * ROWB;
#pragma unroll
            for (int m = 0; m < 8; ++m) {
                const int gcol = A + 2 * (tx + 8 * m);
                const bool ok  = rowok && ((unsigned)gcol < NYL);
                const int dst  = swz_unit(thcu + 4 * m) * 16 + half8;
                __pipeline_memcpy_async(rb + dst,
                                        ok ? grow + gcol : (const float*)xc,
                                        8, ok ? 0 : 8);
            }
            if (tx < 6) {   // tail: dword pairs 64..69
                const int gcol = A + 2 * (tx + 64);
                const bool ok  = rowok && ((unsigned)gcol < NYL);
                const int dst  = swz_unit(thcu + 32) * 16 + half8;
                __pipeline_memcpy_async(rb + dst,
                                        ok ? grow + gcol : (const float*)xc,
                                        8, ok ? 0 : 8);
            }
        }
        if (tid < 81)
            __pipeline_memcpy_async(wbuf + wdoff,
                                    ((const ull*)g_w2)
                                        + (size_t)(o * NC_ + c) * 81 + tid,
                                    8);
        __pipeline_commit();
    };

    // per-thread swizzled E unit byte offsets for row 2typ (row-independent)
    int offs[5];
#pragma unroll
    for (int e = 0; e < 5; ++e)
        offs[e] = (2 * typ) * ROWB + swz_unit(2 * txc + e) * 16;

    ull a0A[4], a0B[5], a1A[4], a1B[5];
#pragma unroll
    for (int j = 0; j < 4; ++j) { a0A[j] = 0ull; a1A[j] = 0ull; }
#pragma unroll
    for (int i = 0; i < 5; ++i) { a0B[i] = 0ull; a1B[i] = 0ull; }

    stage(0, buf0, wb0);
    __pipeline_wait_prior(0);
    __syncthreads();

    for (int c = 0; c < NC_; ++c) {
        if (c + 1 < NC_)
            stage(c + 1, (c & 1) ? buf0 : buf1, (c & 1) ? wb0 : wb1);

        const char* tb = (c & 1) ? buf1 : buf0;
        const char* wb = (c & 1) ? wb1 : wb0;

        if (s_ori[c] & 1) channel_math<1>(tb, wb, offs, a0A, a0B, a1A, a1B);
        else              channel_math<0>(tb, wb, offs, a0A, a0B, a1A, a1B);

        __pipeline_wait_prior(0);
        __syncthreads();
    }

    // ---- epilogue: merge dual-phase accumulators, write 2 rows x 8 cols ----
    const size_t orow = (size_t)(b * NO_ + o) * NXL + (i0 + 2 * typ);
    float* op0 = out + orow * NYL + j0 + txc * 8;
    float* op1 = op0 + NYL;
    float r0[8], r1[8];
#pragma unroll
    for (int j = 0; j < 4; ++j) {
        r0[2*j]   = __uint_as_float((unsigned)(a0A[j] & 0xffffffffull))
                  + __uint_as_float((unsigned)(a0B[j] >> 32));
        r0[2*j+1] = __uint_as_float((unsigned)(a0A[j] >> 32))
                  + __uint_as_float((unsigned)(a0B[j+1] & 0xffffffffull));
        r1[2*j]   = __uint_as_float((unsigned)(a1A[j] & 0xffffffffull))
                  + __uint_as_float((unsigned)(a1B[j] >> 32));
        r1[2*j+1] = __uint_as_float((unsigned)(a1A[j] >> 32))
                  + __uint_as_float((unsigned)(a1B[j+1] & 0xffffffffull));
    }
    reinterpret_cast<float4*>(op0)[0] = make_float4(r0[0], r0[1], r0[2], r0[3]);
    reinterpret_cast<float4*>(op0)[1] = make_float4(r0[4], r0[5], r0[6], r0[7]);
    reinterpret_cast<float4*>(op1)[0] = make_float4(r1[0], r1[1], r1[2], r1[3]);
    reinterpret_cast<float4*>(op1)[1] = make_float4(r1[4], r1[5], r1[6], r1[7]);
}

// ---------------------------------------------------------------------------
extern "C" void kernel_launch(void* const* d_in, const int* in_sizes, int n_in,
                              void* d_out, int out_size) {
    const float* x   = (const float*)d_in[0];
    const float* vk  = (const float*)d_in[1];
    const int*   loc = (const int*)d_in[2];
    float* out = (float*)d_out;

    cudaFuncSetAttribute(conv_kernel,
                         cudaFuncAttributeMaxDynamicSharedMemorySize,
                         SMEM_BYTES);

    prep_all<<<(NG_ * 32 + 255) / 256, 256>>>(vk, loc);

    dim3 grid((NXL / TH) * (NYL / TW), NO_, 16);  // (16, 3, 16)
    conv_kernel<<<grid, 256, SMEM_BYTES>>>(x, out);
}

// round 12
// speedup vs baseline: 1.0596x; 1.0169x over previous
#include <cuda_runtime.h>
#include <cuda_pipeline.h>

typedef unsigned long long ull;

// Problem dims
#define NC_  31
#define NXL  256
#define NYL  256
#define NO_  3
#define KXL  17
#define KYL  17
#define NG_  (NO_ * NC_)   // 93
#define WIN_ 9

// Compact weights: per (o,c) group a 9x9 tile of broadcast (v,v) float2 pairs
__device__ float2 g_w2[NG_ * 81];
__device__ int    g_ori[NG_];   // (kx0 << 8) | ky0

// ---------------------------------------------------------------------------
// Fused prep: one warp per group (origin via shfl-min, then scatter).
// ---------------------------------------------------------------------------
__global__ void prep_all(const float* __restrict__ vk,
                         const int* __restrict__ loc) {
    int w    = (blockIdx.x * blockDim.x + threadIdx.x) >> 5;
    int lane = threadIdx.x & 31;
    if (w >= NG_) return;

    int kxm = 1 << 30, kym = 1 << 30;
    int idxs[3]; float vs[3];
#pragma unroll
    for (int s = 0; s < 3; ++s) {
        int t = lane + 32 * s;
        if (t < 81) {
            int idx = loc[w * 81 + t];
            idxs[s] = idx;
            vs[s]   = vk[w * 81 + t];
            int ky = idx % KYL;
            int kx = (idx / KYL) % KXL;
            kxm = min(kxm, kx);
            kym = min(kym, ky);
        }
    }
#pragma unroll
    for (int off = 16; off; off >>= 1) {
        kxm = min(kxm, __shfl_xor_sync(0xffffffffu, kxm, off));
        kym = min(kym, __shfl_xor_sync(0xffffffffu, kym, off));
    }
    if (lane == 0) g_ori[w] = (kxm << 8) | kym;

#pragma unroll
    for (int s = 0; s < 3; ++s) {
        int t = lane + 32 * s;
        if (t < 81) {
            int idx = idxs[s];
            float v = fmaxf(vs[s], 0.0f);
            int ky = idx % KYL;
            int kx = (idx / KYL) % KXL;
            g_w2[w * 81 + (kx - kxm) * WIN_ + (ky - kym)] = make_float2(v, v);
        }
    }
}

// ---------------------------------------------------------------------------
// Persistent conv, r9 math core. 444 blocks; block k statically owns tiles
// k and k+444. Tile t = ((b*3+o)*8+ir)*2+jc -> 32x128 output tile.
// All buffer selection via scalar ternaries (SEL, never indexed arrays).
// Per channel: 8B-aligned cp.async staging (parity absorbed by dual-phase
// accumulators), in-place register-pipelined LDS.128 operands, fma.rn.f32x2.
// Cross-tile: channel 0 of the next tile staged during the last channel.
// ---------------------------------------------------------------------------
#define TH 32
#define TW 128
#define NTILES 768
#define NBLOCKS 444
#define SRO 40                 // staged rows (TH + 8)
#define SWF 160                // smem row stride in floats
#define ROWB (SWF * 4)         // 640 bytes
#define TILE_B (SRO * ROWB)    // 25600 bytes
#define WPAD 10                // weight row stride in ull
#define WBUF (WIN_ * WPAD)     // 90 ull
#define SMEM_BYTES (2 * TILE_B + 2 * WBUF * 8 + NG_ * 4)  // 53012

#define FMA2(acc, a, b) \
    asm("fma.rn.f32x2 %0, %1, %2, %0;" : "+l"(acc) : "l"(a), "l"(b))

__device__ __forceinline__ int swz_unit(int cu) {
    return cu ^ ((cu >> 3) & 7);
}

__device__ __forceinline__ void ldE(const char* p, ull& a, ull& b) {
    longlong2 L = *(const longlong2*)p;
    a = (ull)L.x; b = (ull)L.y;
}

__device__ __forceinline__ void fmaA(ull* acc, const ull* p, ull w) {
#pragma unroll
    for (int j = 0; j < 8; ++j) FMA2(acc[j], p[j], w);
}
__device__ __forceinline__ void fmaB(ull* acc, const ull* p, ull w) {
#pragma unroll
    for (int i = 0; i < 9; ++i) FMA2(acc[i], p[i], w);
}

// Channel math, parity SV = ky0 & 1 (r9 core, unchanged).
template<int SV>
__device__ __forceinline__ void channel_math(
        const char* __restrict__ tb, const char* __restrict__ wb,
        const int* offs, ull* accA, ull* accB) {
    ull P[14];
#pragma unroll
    for (int e = 0; e < (SV ? 7 : 6); ++e)
        ldE(tb + offs[e], P[2 * e], P[2 * e + 1]);
    ull wp0, wp1;
    ldE(wb, wp0, wp1);                        // taps 0,1 of u=0

#pragma unroll
    for (int u = 0; u < 9; ++u) {
        const char* wr = wb + u * 80;
        const int rn = (u + 1) * ROWB;
        ull w2, w3, w4, w5, w6, w7;
        ldE(wr + 16, w2, w3);

        if (SV == 0) { fmaA(accA, P + 0, wp0); fmaB(accB, P + 0, wp1); }
        else         { fmaB(accB, P + 0, wp0); fmaA(accA, P + 1, wp1); }

        ldE(wr + 32, w4, w5);
        ldE(wr + 48, w6, w7);
        const ull w8 = *(const ull*)(wr + 64);

        if (SV == 0) { fmaA(accA, P + 1, w2); fmaB(accB, P + 1, w3); }
        else         { fmaB(accB, P + 1, w2); fmaA(accA, P + 2, w3); }

        if (u < 8) ldE(tb + offs[0] + rn, P[0], P[1]);   // unit0 next row

        if (SV == 0) { fmaA(accA, P + 2, w4); fmaB(accB, P + 2, w5); }
        else         { fmaB(accB, P + 2, w4); fmaA(accA, P + 3, w5); }

        if (SV == 0) { fmaA(accA, P + 3, w6); fmaB(accB, P + 3, w7); }
        else         { fmaB(accB, P + 3, w6); fmaA(accA, P + 4, w7); }

        if (u < 8) {
            ldE(tb + offs[1] + rn, P[2], P[3]);          // unit1 next row
            ldE(wr + 80, wp0, wp1);                      // taps 0,1 of u+1
        }

        if (SV == 0) fmaA(accA, P + 4, w8);
        else         fmaB(accB, P + 4, w8);

        if (u < 8) {                                     // units 2..5(6) next
            ldE(tb + offs[2] + rn, P[4],  P[5]);
            ldE(tb + offs[3] + rn, P[6],  P[7]);
            ldE(tb + offs[4] + rn, P[8],  P[9]);
            ldE(tb + offs[5] + rn, P[10], P[11]);
            if (SV == 1) ldE(tb + offs[6] + rn, P[12], P[13]);
        }
    }
}

__global__ void __launch_bounds__(256, 3) conv_kernel(
        const float* __restrict__ x, float* __restrict__ out) {
    extern __shared__ float smem[];
    char* buf0 = (char*)smem;
    char* buf1 = buf0 + TILE_B;
    char* wb0  = buf1 + TILE_B;
    char* wb1  = wb0 + WBUF * 8;
    int*  s_ori = (int*)(wb1 + WBUF * 8);

    const int tid = threadIdx.x;
    const int tx  = tid & 7;          // 16-col group
    const int ty  = tid >> 3;         // output row 0..31

    for (int i = tid; i < NG_; i += 256) s_ori[i] = g_ori[i];
    __syncthreads();

    const int wdoff = ((tid / WIN_) * WPAD + tid % WIN_) * 8;
    const int half8 = (tx & 1) * 8;
    const int thcu  = tx >> 1;

    // stage channel c of group g=(o*NC_+c) for tile at (b, i0, j0)
    auto stage = [&](int b, int g, int i0, int j0, char* tbuf, char* wbuf) {
        const int ori = s_ori[g];
        const int kx0 = ori >> 8, ky0 = ori & 255;
        const int A   = j0 + (ky0 & ~1) - 8;   // even, 8B-aligned gmem origin
        const int ri0 = i0 + kx0 - 8;
        const float* __restrict__ xc =
            x + ((size_t)b * NC_ + (g % NC_)) * (NXL * NYL);
#pragma unroll
        for (int pass = 0; pass < 2; ++pass) {
            if (pass == 1 && ty >= 8) break;
            const int r  = ty + pass * 32;
            const int gi = ri0 + r;
            const bool rowok = (unsigned)gi < NXL;
            const float* grow = xc + (rowok ? gi : 0) * NYL;
            char* rb = tbuf + r * ROWB;
#pragma unroll
            for (int m = 0; m < 8; ++m) {
                const int gcol = A + 2 * (tx + 8 * m);
                const bool ok  = rowok && ((unsigned)gcol < NYL);
                const int dst  = swz_unit(thcu + 4 * m) * 16 + half8;
                __pipeline_memcpy_async(rb + dst,
                                        ok ? grow + gcol : (const float*)xc,
                                        8, ok ? 0 : 8);
            }
            if (tx < 6) {   // tail: dword pairs 64..69
                const int gcol = A + 2 * (tx + 64);
                const bool ok  = rowok && ((unsigned)gcol < NYL);
                const int dst  = swz_unit(thcu + 32) * 16 + half8;
                __pipeline_memcpy_async(rb + dst,
                                        ok ? grow + gcol : (const float*)xc,
                                        8, ok ? 0 : 8);
            }
        }
        if (tid < 81)
            __pipeline_memcpy_async(wbuf + wdoff,
                                    ((const ull*)g_w2) + (size_t)g * 81 + tid,
                                    8);
        __pipeline_commit();
    };

    // per-thread swizzled E unit byte offsets (row-independent)
    int offs[7];
#pragma unroll
    for (int e = 0; e < 7; ++e)
        offs[e] = ty * ROWB + swz_unit(4 * tx + e) * 16;

    // ---- persistent loop: tiles blockIdx.x and blockIdx.x + NBLOCKS ----
    int t = blockIdx.x;
    {
        const int bo = t >> 4;
        const int b0 = bo / 3, o0 = bo - 3 * b0;
        stage(b0, o0 * NC_, ((t >> 1) & 7) * TH, (t & 1) * TW, buf0, wb0);
        __pipeline_wait_prior(0);
        __syncthreads();
    }

    bool flip = false;
    while (true) {
        const int jc = t & 1, ir = (t >> 1) & 7, bo = t >> 4;
        const int b = bo / 3, o = bo - 3 * b;
        const int i0 = ir * TH, j0 = jc * TW;
        const int tn = t + NBLOCKS;
        const bool more = tn < NTILES;

        ull accA[8], accB[9];
#pragma unroll
        for (int j = 0; j < 8; ++j) accA[j] = 0ull;
#pragma unroll
        for (int i = 0; i < 9; ++i) accB[i] = 0ull;

        for (int c = 0; c < NC_; ++c) {
            char* nb  = flip ? buf0 : buf1;
            char* nwb = flip ? wb0  : wb1;
            if (c + 1 < NC_) {
                stage(b, o * NC_ + c + 1, i0, j0, nb, nwb);
            } else if (more) {
                const int bo2 = tn >> 4;
                const int b2 = bo2 / 3, o2 = bo2 - 3 * b2;
                stage(b2, o2 * NC_, ((tn >> 1) & 7) * TH, (tn & 1) * TW,
                      nb, nwb);
            }

            const char* tb = flip ? buf1 : buf0;
            const char* wb = flip ? wb1  : wb0;
            if (s_ori[o * NC_ + c] & 1)
                channel_math<1>(tb, wb, offs, accA, accB);
            else
                channel_math<0>(tb, wb, offs, accA, accB);

            __pipeline_wait_prior(0);
            __syncthreads();
            flip = !flip;
        }

        // epilogue: merge dual-phase accumulators, write 16 cols
        float res[16];
#pragma unroll
        for (int j = 0; j < 8; ++j) {
            float aLo = __uint_as_float((unsigned)(accA[j] & 0xffffffffull));
            float aHi = __uint_as_float((unsigned)(accA[j] >> 32));
            float bHi = __uint_as_float((unsigned)(accB[j] >> 32));
            float bLo = __uint_as_float((unsigned)(accB[j + 1] & 0xffffffffull));
            res[2 * j]     = aLo + bHi;
            res[2 * j + 1] = aHi + bLo;
        }
        float* op = out + ((size_t)(b * NO_ + o) * NXL + (i0 + ty)) * NYL
                        + j0 + tx * 16;
#pragma unroll
        for (int q = 0; q < 4; ++q)
            reinterpret_cast<float4*>(op)[q] =
                make_float4(res[4 * q], res[4 * q + 1],
                            res[4 * q + 2], res[4 * q + 3]);

        if (!more) break;
        t = tn;   // its channel 0 is already resident in the current buffer
    }
}

// ---------------------------------------------------------------------------
extern "C" void kernel_launch(void* const* d_in, const int* in_sizes, int n_in,
                              void* d_out, int out_size) {
    const float* x   = (const float*)d_in[0];
    const float* vk  = (const float*)d_in[1];
    const int*   loc = (const int*)d_in[2];
    float* out = (float*)d_out;

    cudaFuncSetAttribute(conv_kernel,
                         cudaFuncAttributeMaxDynamicSharedMemorySize,
                         SMEM_BYTES);

    prep_all<<<(NG_ * 32 + 255) / 256, 256>>>(vk, loc);
    conv_kernel<<<NBLOCKS, 256, SMEM_BYTES>>>(x, out);
}